// round 1
// baseline (speedup 1.0000x reference)
#include <cuda_runtime.h>

#define B_   256
#define NI   64
#define L_   128
#define H_   128
#define K_   40
#define GATES 384

typedef unsigned long long ull;

// Transposed weights: wT[k][g] = w[g][k].  129 rows: +1 row so the
// ping-pong prefetch may harmlessly overfetch row 128.
__device__ __align__(16) float g_wTi[129 * GATES];
__device__ __align__(16) float g_wTh[129 * GATES];

__device__ __forceinline__ ull pk2(float v) {
    ull r; asm("mov.b64 %0, {%1, %1};" : "=l"(r) : "f"(v)); return r;
}
__device__ __forceinline__ float2 upk(ull v) {
    float2 f; asm("mov.b64 {%0, %1}, %2;" : "=f"(f.x), "=f"(f.y) : "l"(v)); return f;
}
__device__ __forceinline__ void fma2(ull& d, ull a, ull b) {
    asm("fma.rn.f32x2 %0, %1, %2, %0;" : "+l"(d) : "l"(a), "l"(b));
}
__device__ __forceinline__ ull ld2(const float* p) {
    return *reinterpret_cast<const ull*>(p);
}

__device__ __forceinline__ float sigm(float x) {
    return __fdividef(1.0f, 1.0f + __expf(-x));
}
__device__ __forceinline__ float tanh_(float x) {
    return __fdividef(2.0f, 1.0f + __expf(-2.0f * x)) - 1.0f;
}

// ---------------------------------------------------------------------------
// Prep: transpose both GRU weight matrices (384x128 -> 128x384).
// ---------------------------------------------------------------------------
__global__ void prep_kernel(const float* __restrict__ w_ih,
                            const float* __restrict__ w_hh) {
    int idx = blockIdx.x * blockDim.x + threadIdx.x;
    if (idx < GATES * H_) {
        int g  = idx >> 7;     // gate row 0..383
        int kk = idx & 127;    // input col 0..127
        g_wTi[kk * GATES + g] = w_ih[idx];
        g_wTh[kk * GATES + g] = w_hh[idx];
    }
}

// ---------------------------------------------------------------------------
// Fused: gather -> adj^T GEMM (+bias) -> 2x GRU pass.  One block per batch.
// 256 threads = 8 warps x 5 rows.  Lane owns column pairs (2*lane, 2*lane+64).
// ---------------------------------------------------------------------------
__global__ __launch_bounds__(256, 1)
void fused_kernel(const float* __restrict__ seq_out,
                  const int*   __restrict__ target_idxs,
                  const int*   __restrict__ nid2rows,
                  const int*   __restrict__ ev_nids,
                  const float* __restrict__ adj,
                  const float* __restrict__ adj_bias,
                  const float* __restrict__ b_ih,
                  const float* __restrict__ b_hh,
                  float*       __restrict__ out) {
    __shared__ float s_h[K_ * H_];     // ev / h buffer (20 KB)
    __shared__ float s_x[K_ * H_];     // a  / x buffer (20 KB)
    __shared__ float s_adj[K_ * K_];   // 6.4 KB

    const int b    = blockIdx.x;
    const int tid  = threadIdx.x;
    const int warp = tid >> 5;
    const int lane = tid & 31;
    const int r0   = warp * 5;                // this warp's 5 rows
    const int c0   = lane * 2;                // column pair 0
    const int c1   = lane * 2 + 64;           // column pair 1

    // ---- Phase A: load adj tile + gather ev rows into s_h -----------------
    for (int i = tid; i < K_ * K_; i += 256)
        s_adj[i] = adj[b * K_ * K_ + i];

    #pragma unroll
    for (int rr = 0; rr < 5; rr++) {
        int k   = r0 + rr;
        int nid = ev_nids[b * K_ + k];
        int row = nid2rows[b * NI + nid];
        long long gi = (long long)b * NI + row;
        int t   = target_idxs[gi];
        const float4* src = reinterpret_cast<const float4*>(
            seq_out + (gi * L_ + t) * (long long)H_);
        reinterpret_cast<float4*>(s_h + k * H_)[lane] = src[lane];
    }
    __syncthreads();

    // ---- Phase B: a[j][c] = sum_i adj[i][j] * ev[i][c] + bias[c] ----------
    {
        ull bias0 = ld2(adj_bias + c0);
        ull bias1 = ld2(adj_bias + c1);
        ull acc[5][2];
        #pragma unroll
        for (int r = 0; r < 5; r++) { acc[r][0] = bias0; acc[r][1] = bias1; }

        for (int i = 0; i < K_; i++) {
            ull e0 = ld2(s_h + i * H_ + c0);
            ull e1 = ld2(s_h + i * H_ + c1);
            #pragma unroll
            for (int r = 0; r < 5; r++) {
                ull av = pk2(s_adj[i * K_ + r0 + r]);
                fma2(acc[r][0], av, e0);
                fma2(acc[r][1], av, e1);
            }
        }
        #pragma unroll
        for (int r = 0; r < 5; r++) {
            *reinterpret_cast<ull*>(s_x + (r0 + r) * H_ + c0) = acc[r][0];
            *reinterpret_cast<ull*>(s_x + (r0 + r) * H_ + c1) = acc[r][1];
        }
    }
    __syncthreads();

    // ---- GRU pass (inlined twice via lambda) -------------------------------
    // acc gate index: 0=i_r 1=i_z 2=i_n 3=h_r 4=h_z 5=h_n
    auto gru_pass = [&](const float* __restrict__ xb, float* __restrict__ hg) {
        ull acc[5][2][6];
        #pragma unroll
        for (int g = 0; g < 3; g++) {
            ull bi0 = ld2(b_ih + g * H_ + c0), bi1 = ld2(b_ih + g * H_ + c1);
            ull bh0 = ld2(b_hh + g * H_ + c0), bh1 = ld2(b_hh + g * H_ + c1);
            #pragma unroll
            for (int r = 0; r < 5; r++) {
                acc[r][0][g]     = bi0; acc[r][1][g]     = bi1;
                acc[r][0][3 + g] = bh0; acc[r][1][3 + g] = bh1;
            }
        }

        const float* pA = g_wTi + c0;   // w_ih pair0
        const float* pB = g_wTi + c1;   // w_ih pair1
        const float* pC = g_wTh + c0;   // w_hh pair0
        const float* pD = g_wTh + c1;   // w_hh pair1

        ull wa[12], wb[12];
        auto loadw = [&](ull* w, int kk) {
            const float* a = pA + kk * GATES;
            const float* p = pB + kk * GATES;
            const float* c = pC + kk * GATES;
            const float* d = pD + kk * GATES;
            #pragma unroll
            for (int g = 0; g < 3; g++) {
                w[g]     = ld2(a + g * H_);
                w[3 + g] = ld2(p + g * H_);
                w[6 + g] = ld2(c + g * H_);
                w[9 + g] = ld2(d + g * H_);
            }
        };
        auto body = [&](const ull* w, const float2* xf, const float2* hf, bool hi) {
            #pragma unroll
            for (int r = 0; r < 5; r++) {
                ull x2 = pk2(hi ? xf[r].y : xf[r].x);
                ull h2 = pk2(hi ? hf[r].y : hf[r].x);
                #pragma unroll
                for (int g = 0; g < 3; g++) {
                    fma2(acc[r][0][g],     x2, w[g]);
                    fma2(acc[r][1][g],     x2, w[3 + g]);
                    fma2(acc[r][0][3 + g], h2, w[6 + g]);
                    fma2(acc[r][1][3 + g], h2, w[9 + g]);
                }
            }
        };

        loadw(wa, 0);
        for (int kk = 0; kk < H_; kk += 2) {
            loadw(wb, kk + 1);
            float2 xf[5], hf[5];
            #pragma unroll
            for (int r = 0; r < 5; r++) {        // broadcast LDS.64: 2 kk at once
                xf[r] = upk(ld2(xb  + (r0 + r) * H_ + kk));
                hf[r] = upk(ld2(s_h + (r0 + r) * H_ + kk));
            }
            body(wa, xf, hf, false);
            loadw(wa, kk + 2);                   // overfetch @126 hits pad row
            body(wb, xf, hf, true);
        }

        // epilogue: gates + state update
        #pragma unroll
        for (int r = 0; r < 5; r++) {
            int row = r0 + r;
            #pragma unroll
            for (int p = 0; p < 2; p++) {
                int c = p ? c1 : c0;
                float2 ir = upk(acc[r][p][0]);
                float2 iz = upk(acc[r][p][1]);
                float2 in_ = upk(acc[r][p][2]);
                float2 hr = upk(acc[r][p][3]);
                float2 hz = upk(acc[r][p][4]);
                float2 hn = upk(acc[r][p][5]);
                float2 hold = *reinterpret_cast<const float2*>(s_h + row * H_ + c);
                float rx = sigm(ir.x + hr.x), ry = sigm(ir.y + hr.y);
                float zx = sigm(iz.x + hz.x), zy = sigm(iz.y + hz.y);
                float nx = tanh_(in_.x + rx * hn.x), ny = tanh_(in_.y + ry * hn.y);
                float2 hnew;
                hnew.x = (1.0f - zx) * nx + zx * hold.x;
                hnew.y = (1.0f - zy) * ny + zy * hold.y;
                if (hg)
                    *reinterpret_cast<float2*>(hg + row * H_ + c) = hnew;
                else
                    *reinterpret_cast<float2*>(s_h + row * H_ + c) = hnew;
            }
        }
    };

    gru_pass(s_x, nullptr);                       // pass 1: x=a, h=ev -> s_h
    __syncwarp();
    gru_pass(s_h, out + (long long)b * K_ * H_);  // pass 2: x=h=s_h -> gmem
}

// ---------------------------------------------------------------------------
extern "C" void kernel_launch(void* const* d_in, const int* in_sizes, int n_in,
                              void* d_out, int out_size) {
    const float* seq_out     = (const float*)d_in[0];
    const int*   target_idxs = (const int*)  d_in[1];
    const int*   nid2rows    = (const int*)  d_in[2];
    const int*   ev_nids     = (const int*)  d_in[3];
    const float* adj         = (const float*)d_in[4];
    const float* adj_bias    = (const float*)d_in[5];
    const float* w_ih        = (const float*)d_in[6];
    const float* w_hh        = (const float*)d_in[7];
    const float* b_ih        = (const float*)d_in[8];
    const float* b_hh        = (const float*)d_in[9];
    float* out = (float*)d_out;

    prep_kernel<<<(GATES * H_ + 255) / 256, 256>>>(w_ih, w_hh);
    fused_kernel<<<B_, 256>>>(seq_out, target_idxs, nid2rows, ev_nids,
                              adj, adj_bias, b_ih, b_hh, out);
}

// round 2
// speedup vs baseline: 1.0964x; 1.0964x over previous
#include <cuda_runtime.h>

#define B_   256
#define NI   64
#define L_   128
#define H_   128
#define K_   40
#define GATES 384

typedef unsigned long long ull;

// Transposed weights: wT[k][g] = w[g][k].  129 rows: +1 pad row so the
// ping-pong prefetch may harmlessly overfetch row 128.
__device__ __align__(16) float g_wTi[129 * GATES];
__device__ __align__(16) float g_wTh[129 * GATES];

__device__ __forceinline__ ull pk2(float v) {
    ull r; asm("mov.b64 %0, {%1, %1};" : "=l"(r) : "f"(v)); return r;
}
__device__ __forceinline__ float2 upk(ull v) {
    float2 f; asm("mov.b64 {%0, %1}, %2;" : "=f"(f.x), "=f"(f.y) : "l"(v)); return f;
}
__device__ __forceinline__ void fma2(ull& d, ull a, ull b) {
    asm("fma.rn.f32x2 %0, %1, %2, %0;" : "+l"(d) : "l"(a), "l"(b));
}
__device__ __forceinline__ ull ld2(const float* p) {
    return *reinterpret_cast<const ull*>(p);
}

__device__ __forceinline__ float sigm(float x) {
    return __fdividef(1.0f, 1.0f + __expf(-x));
}
__device__ __forceinline__ float tanh_(float x) {
    return __fdividef(2.0f, 1.0f + __expf(-2.0f * x)) - 1.0f;
}

// ---------------------------------------------------------------------------
// Prep: transpose both GRU weight matrices (384x128 -> 128x384).
// ---------------------------------------------------------------------------
__global__ void prep_kernel(const float* __restrict__ w_ih,
                            const float* __restrict__ w_hh) {
    int idx = blockIdx.x * blockDim.x + threadIdx.x;
    if (idx < GATES * H_) {
        int g  = idx >> 7;     // gate row 0..383
        int kk = idx & 127;    // input col 0..127
        g_wTi[kk * GATES + g] = w_ih[idx];
        g_wTh[kk * GATES + g] = w_hh[idx];
    }
}

// ---------------------------------------------------------------------------
// Fused: gather -> adj^T GEMM (+bias) -> 2x GRU pass.  One block per batch.
// 512 threads = 16 warps.  Warp = (row-group rw = warp>>1, pair-group p = warp&1).
// Warp owns 5 rows x 64 columns; lane owns column pair c0 = 2*lane + 64*p.
// Per-thread: 30 ull accumulators (5 rows x 6 gate-dots).
// ---------------------------------------------------------------------------
__global__ __launch_bounds__(512, 1)
void fused_kernel(const float* __restrict__ seq_out,
                  const int*   __restrict__ target_idxs,
                  const int*   __restrict__ nid2rows,
                  const int*   __restrict__ ev_nids,
                  const float* __restrict__ adj,
                  const float* __restrict__ adj_bias,
                  const float* __restrict__ b_ih,
                  const float* __restrict__ b_hh,
                  float*       __restrict__ out) {
    __shared__ float s_h[K_ * H_];     // ev / h buffer (20 KB)
    __shared__ float s_x[K_ * H_];     // a  / x buffer (20 KB)
    __shared__ float s_adj[K_ * K_];   // 6.4 KB

    const int b    = blockIdx.x;
    const int tid  = threadIdx.x;
    const int warp = tid >> 5;
    const int lane = tid & 31;
    const int rw   = warp >> 1;               // row group 0..7
    const int p    = warp & 1;                // pair group 0..1
    const int r0   = rw * 5;                  // this warp's 5 rows
    const int c0   = lane * 2 + p * 64;       // this lane's column pair

    // ---- Phase A: load adj tile + gather ev rows into s_h -----------------
    for (int i = tid; i < K_ * K_; i += 512)
        s_adj[i] = adj[b * K_ * K_ + i];

    if (p == 0) {                              // 8 warps x 5 rows = 40 rows
        #pragma unroll
        for (int rr = 0; rr < 5; rr++) {
            int k   = r0 + rr;
            int nid = ev_nids[b * K_ + k];
            int row = nid2rows[b * NI + nid];
            long long gi = (long long)b * NI + row;
            int t   = target_idxs[gi];
            const float4* src = reinterpret_cast<const float4*>(
                seq_out + (gi * L_ + t) * (long long)H_);
            reinterpret_cast<float4*>(s_h + k * H_)[lane] = src[lane];
        }
    }
    __syncthreads();

    // ---- Phase B: a[j][c] = sum_i adj[i][j] * ev[i][c] + bias[c] ----------
    {
        ull biasv = ld2(adj_bias + c0);
        ull acc[5];
        #pragma unroll
        for (int r = 0; r < 5; r++) acc[r] = biasv;

        for (int i = 0; i < K_; i++) {
            ull e = ld2(s_h + i * H_ + c0);
            #pragma unroll
            for (int r = 0; r < 5; r++) {
                ull av = pk2(s_adj[i * K_ + r0 + r]);
                fma2(acc[r], av, e);
            }
        }
        #pragma unroll
        for (int r = 0; r < 5; r++)
            *reinterpret_cast<ull*>(s_x + (r0 + r) * H_ + c0) = acc[r];
    }
    __syncthreads();

    // ---- GRU pass (inlined twice via lambda) -------------------------------
    // acc gate index: 0=i_r 1=i_z 2=i_n 3=h_r 4=h_z 5=h_n
    auto gru_pass = [&](const float* __restrict__ xb, bool to_gmem) {
        ull acc[5][6];
        #pragma unroll
        for (int g = 0; g < 3; g++) {
            ull bi = ld2(b_ih + g * H_ + c0);
            ull bh = ld2(b_hh + g * H_ + c0);
            #pragma unroll
            for (int r = 0; r < 5; r++) { acc[r][g] = bi; acc[r][3 + g] = bh; }
        }

        const float* pi = g_wTi + c0;
        const float* ph = g_wTh + c0;

        ull wa[6], wb[6];
        auto loadw = [&](ull* w, int kk) {
            const float* a = pi + kk * GATES;
            const float* c = ph + kk * GATES;
            #pragma unroll
            for (int g = 0; g < 3; g++) {
                w[g]     = ld2(a + g * H_);
                w[3 + g] = ld2(c + g * H_);
            }
        };
        auto body = [&](const ull* w, const float2* xf, const float2* hf, bool hi) {
            #pragma unroll
            for (int r = 0; r < 5; r++) {
                ull x2 = pk2(hi ? xf[r].y : xf[r].x);
                ull h2 = pk2(hi ? hf[r].y : hf[r].x);
                #pragma unroll
                for (int g = 0; g < 3; g++) {
                    fma2(acc[r][g],     x2, w[g]);
                    fma2(acc[r][3 + g], h2, w[3 + g]);
                }
            }
        };

        loadw(wa, 0);
        for (int kk = 0; kk < H_; kk += 2) {
            loadw(wb, kk + 1);
            float2 xf[5], hf[5];
            #pragma unroll
            for (int r = 0; r < 5; r++) {        // broadcast LDS.64: 2 kk at once
                xf[r] = upk(ld2(xb  + (r0 + r) * H_ + kk));
                hf[r] = upk(ld2(s_h + (r0 + r) * H_ + kk));
            }
            body(wa, xf, hf, false);
            loadw(wa, kk + 2);                   // overfetch @126 hits pad row
            body(wb, xf, hf, true);
        }

        // epilogue: gates + state update (into registers first)
        ull hnew[5];
        #pragma unroll
        for (int r = 0; r < 5; r++) {
            int row = r0 + r;
            float2 ir = upk(acc[r][0]);
            float2 iz = upk(acc[r][1]);
            float2 in_ = upk(acc[r][2]);
            float2 hr = upk(acc[r][3]);
            float2 hz = upk(acc[r][4]);
            float2 hn = upk(acc[r][5]);
            float2 hold = upk(ld2(s_h + row * H_ + c0));
            float rx = sigm(ir.x + hr.x), ry = sigm(ir.y + hr.y);
            float zx = sigm(iz.x + hz.x), zy = sigm(iz.y + hz.y);
            float nx = tanh_(in_.x + rx * hn.x), ny = tanh_(in_.y + ry * hn.y);
            float2 hv;
            hv.x = (1.0f - zx) * nx + zx * hold.x;
            hv.y = (1.0f - zy) * ny + zy * hold.y;
            hnew[r] = *reinterpret_cast<ull*>(&hv);
        }

        if (to_gmem) {
            #pragma unroll
            for (int r = 0; r < 5; r++)
                *reinterpret_cast<ull*>(out + (long long)b * K_ * H_
                                        + (r0 + r) * H_ + c0) = hnew[r];
        } else {
            // sibling pair-warps read all columns of our rows during the K
            // loop; barrier before overwriting s_h, barrier again before use.
            __syncthreads();
            #pragma unroll
            for (int r = 0; r < 5; r++)
                *reinterpret_cast<ull*>(s_h + (r0 + r) * H_ + c0) = hnew[r];
            __syncthreads();
        }
    };

    gru_pass(s_x, false);                       // pass 1: x=a,  h=ev -> s_h
    gru_pass(s_h, true);                        // pass 2: x=h=s_h     -> gmem
}

// ---------------------------------------------------------------------------
extern "C" void kernel_launch(void* const* d_in, const int* in_sizes, int n_in,
                              void* d_out, int out_size) {
    const float* seq_out     = (const float*)d_in[0];
    const int*   target_idxs = (const int*)  d_in[1];
    const int*   nid2rows    = (const int*)  d_in[2];
    const int*   ev_nids     = (const int*)  d_in[3];
    const float* adj         = (const float*)d_in[4];
    const float* adj_bias    = (const float*)d_in[5];
    const float* w_ih        = (const float*)d_in[6];
    const float* w_hh        = (const float*)d_in[7];
    const float* b_ih        = (const float*)d_in[8];
    const float* b_hh        = (const float*)d_in[9];
    float* out = (float*)d_out;

    prep_kernel<<<(GATES * H_ + 255) / 256, 256>>>(w_ih, w_hh);
    fused_kernel<<<B_, 512>>>(seq_out, target_idxs, nid2rows, ev_nids,
                              adj, adj_bias, b_ih, b_hh, out);
}

// round 4
// speedup vs baseline: 1.5002x; 1.3683x over previous
#include <cuda_runtime.h>
#include <cuda_bf16.h>
#include <cstdint>

#define B_    256
#define NI    64
#define L_    128
#define H_    128
#define K_    40
#define MTOT  (B_ * K_)          /* 10240 rows */
#define GATES 384

typedef unsigned long long ull;

// ---------------------------------------------------------------------------
// Device scratch
// ---------------------------------------------------------------------------
__device__ __align__(256) __nv_bfloat16 g_xhi[MTOT * H_];
__device__ __align__(256) __nv_bfloat16 g_xlo[MTOT * H_];
__device__ __align__(256) __nv_bfloat16 g_hhi[MTOT * H_];
__device__ __align__(256) __nv_bfloat16 g_hlo[MTOT * H_];
__device__ __align__(256) float         g_h32[MTOT * H_];
__device__ __align__(256) __nv_bfloat16 g_h2hi[MTOT * H_];
__device__ __align__(256) __nv_bfloat16 g_h2lo[MTOT * H_];
__device__ __align__(256) float         g_h232[MTOT * H_];
__device__ __align__(256) __nv_bfloat16 g_wih_hi[GATES * H_];
__device__ __align__(256) __nv_bfloat16 g_wih_lo[GATES * H_];
__device__ __align__(256) __nv_bfloat16 g_whh_hi[GATES * H_];
__device__ __align__(256) __nv_bfloat16 g_whh_lo[GATES * H_];

// ---------------------------------------------------------------------------
// Helpers
// ---------------------------------------------------------------------------
__device__ __forceinline__ uint32_t smem_u32(const void* p) {
    uint32_t a;
    asm("{ .reg .u64 t; cvta.to.shared.u64 t, %1; cvt.u32.u64 %0, t; }"
        : "=r"(a) : "l"(p));
    return a;
}
__device__ __forceinline__ void cp16(uint32_t dst, const void* src) {
    asm volatile("cp.async.cg.shared.global [%0], [%1], 16;"
                 :: "r"(dst), "l"(src) : "memory");
}
#define CP_COMMIT() asm volatile("cp.async.commit_group;" ::: "memory")
#define CP_WAIT0()  asm volatile("cp.async.wait_group 0;" ::: "memory")

__device__ __forceinline__ void ldmA(uint32_t* a, uint32_t addr) {
    asm volatile("ldmatrix.sync.aligned.m8n8.x4.shared.b16 {%0,%1,%2,%3}, [%4];"
                 : "=r"(a[0]), "=r"(a[1]), "=r"(a[2]), "=r"(a[3]) : "r"(addr));
}
__device__ __forceinline__ uint32_t lds32(uint32_t addr) {
    uint32_t v; asm volatile("ld.shared.b32 %0, [%1];" : "=r"(v) : "r"(addr));
    return v;
}
__device__ __forceinline__ float ldsf(uint32_t addr) {
    float v; asm volatile("ld.shared.f32 %0, [%1];" : "=f"(v) : "r"(addr));
    return v;
}
__device__ __forceinline__ void sts2(uint32_t addr, float a, float b) {
    asm volatile("st.shared.v2.f32 [%0], {%1,%2};"
                 :: "r"(addr), "f"(a), "f"(b) : "memory");
}
__device__ __forceinline__ void hmma(float* c, const uint32_t* a,
                                     uint32_t b0, uint32_t b1) {
    asm volatile("mma.sync.aligned.m16n8k16.row.col.f32.bf16.bf16.f32 "
                 "{%0,%1,%2,%3}, {%4,%5,%6,%7}, {%8,%9}, {%0,%1,%2,%3};"
                 : "+f"(c[0]), "+f"(c[1]), "+f"(c[2]), "+f"(c[3])
                 : "r"(a[0]), "r"(a[1]), "r"(a[2]), "r"(a[3]),
                   "r"(b0), "r"(b1));
}

__device__ __forceinline__ ull pk2(float v) {
    ull r; asm("mov.b64 %0, {%1, %1};" : "=l"(r) : "f"(v)); return r;
}
__device__ __forceinline__ float2 upk(ull v) {
    float2 f; asm("mov.b64 {%0, %1}, %2;" : "=f"(f.x), "=f"(f.y) : "l"(v)); return f;
}
__device__ __forceinline__ void fma2(ull& d, ull a, ull b) {
    asm("fma.rn.f32x2 %0, %1, %2, %0;" : "+l"(d) : "l"(a), "l"(b));
}
__device__ __forceinline__ ull ld2(const float* p) { return *(const ull*)p; }

__device__ __forceinline__ float sigm(float x) {
    return __fdividef(1.0f, 1.0f + __expf(-x));
}
__device__ __forceinline__ float tanh_(float x) {
    return __fdividef(2.0f, 1.0f + __expf(-2.0f * x)) - 1.0f;
}
__device__ __forceinline__ void split_store(float v, __nv_bfloat16* hi,
                                            __nv_bfloat16* lo, int idx) {
    __nv_bfloat16 h = __float2bfloat16(v);
    hi[idx] = h;
    lo[idx] = __float2bfloat16(v - __bfloat162float(h));
}

// ---------------------------------------------------------------------------
// K1: split weights into bf16 hi/lo
// ---------------------------------------------------------------------------
__global__ void prep_kernel(const float* __restrict__ w_ih,
                            const float* __restrict__ w_hh) {
    int idx = blockIdx.x * blockDim.x + threadIdx.x;
    if (idx < GATES * H_) {
        split_store(w_ih[idx], g_wih_hi, g_wih_lo, idx);
        split_store(w_hh[idx], g_whh_hi, g_whh_lo, idx);
    }
}

// ---------------------------------------------------------------------------
// K2: gather + adj GEMM -> x (a) splits, h (ev) splits + fp32 hold.
// ---------------------------------------------------------------------------
__global__ __launch_bounds__(256, 1)
void gather_adj_kernel(const float* __restrict__ seq_out,
                       const int*   __restrict__ target_idxs,
                       const int*   __restrict__ nid2rows,
                       const int*   __restrict__ ev_nids,
                       const float* __restrict__ adj,
                       const float* __restrict__ adj_bias) {
    __shared__ float s_h[K_ * H_];
    __shared__ float s_adj[K_ * K_];

    const int b    = blockIdx.x;
    const int tid  = threadIdx.x;
    const int warp = tid >> 5;
    const int lane = tid & 31;
    const int r0   = warp * 5;
    const int c0   = lane * 2;
    const int c1   = lane * 2 + 64;

    for (int i = tid; i < K_ * K_; i += 256)
        s_adj[i] = adj[b * K_ * K_ + i];

    #pragma unroll
    for (int rr = 0; rr < 5; rr++) {
        int k   = r0 + rr;
        int nid = ev_nids[b * K_ + k];
        int row = nid2rows[b * NI + nid];
        long long gi = (long long)b * NI + row;
        int t = target_idxs[gi];
        const float4* src = reinterpret_cast<const float4*>(
            seq_out + (gi * L_ + t) * (long long)H_);
        reinterpret_cast<float4*>(s_h + k * H_)[lane] = src[lane];
    }
    __syncthreads();

    ull bias0 = ld2(adj_bias + c0);
    ull bias1 = ld2(adj_bias + c1);
    ull acc[5][2];
    #pragma unroll
    for (int r = 0; r < 5; r++) { acc[r][0] = bias0; acc[r][1] = bias1; }

    for (int i = 0; i < K_; i++) {
        ull e0 = ld2(s_h + i * H_ + c0);
        ull e1 = ld2(s_h + i * H_ + c1);
        #pragma unroll
        for (int r = 0; r < 5; r++) {
            ull av = pk2(s_adj[i * K_ + r0 + r]);
            fma2(acc[r][0], av, e0);
            fma2(acc[r][1], av, e1);
        }
    }

    #pragma unroll
    for (int r = 0; r < 5; r++) {
        int gr = b * K_ + r0 + r;
        float2 a0 = upk(acc[r][0]);
        float2 a1 = upk(acc[r][1]);
        split_store(a0.x, g_xhi, g_xlo, gr * H_ + c0);
        split_store(a0.y, g_xhi, g_xlo, gr * H_ + c0 + 1);
        split_store(a1.x, g_xhi, g_xlo, gr * H_ + c1);
        split_store(a1.y, g_xhi, g_xlo, gr * H_ + c1 + 1);

        float2 e0 = upk(ld2(s_h + (r0 + r) * H_ + c0));
        float2 e1 = upk(ld2(s_h + (r0 + r) * H_ + c1));
        g_h32[gr * H_ + c0]     = e0.x;
        g_h32[gr * H_ + c0 + 1] = e0.y;
        g_h32[gr * H_ + c1]     = e1.x;
        g_h32[gr * H_ + c1 + 1] = e1.y;
        split_store(e0.x, g_hhi, g_hlo, gr * H_ + c0);
        split_store(e0.y, g_hhi, g_hlo, gr * H_ + c0 + 1);
        split_store(e1.x, g_hhi, g_hlo, gr * H_ + c1);
        split_store(e1.y, g_hhi, g_hlo, gr * H_ + c1 + 1);
    }
}

// ---------------------------------------------------------------------------
// K3: one GRU pass via HMMA (mma.sync m16n8k16 bf16->f32).
// Grid (160, 4): CTA = 64 rows x 32 h-cols (192 gate-cols).
// 8 warps = 2 row-groups x 4 col-chunks (chunks 0-1: gi/x, 2-3: gh/h).
// Warp = 2 m-tiles (32 rows) x 6 n-tiles (48 gate-cols); 48 f32 acc.
// 3 emulation terms: xhi*whi + xhi*wlo + xlo*whi.
// ---------------------------------------------------------------------------
#define PITCH   272                       /* bytes per A/W smem row */
#define A_TSZ   (64 * PITCH)              /* 17408 */
#define SW_OFF  (4 * A_TSZ)               /* 69632 */
#define W_TSZ   (192 * PITCH)             /* 52224 */
#define SG_OFF  SW_OFF                    /* gate buf overlays W */
#define GPITCH  1552                      /* 388 f32 words per gate row */
#define SMEM_TOT (SW_OFF + 2 * W_TSZ)     /* 174080 */

__global__ __launch_bounds__(256, 1)
void gru_pass_kernel(const __nv_bfloat16* __restrict__ xhi,
                     const __nv_bfloat16* __restrict__ xlo,
                     const __nv_bfloat16* __restrict__ hhi,
                     const __nv_bfloat16* __restrict__ hlo,
                     const float* __restrict__ hold,
                     const __nv_bfloat16* __restrict__ wih_hi,
                     const __nv_bfloat16* __restrict__ wih_lo,
                     const __nv_bfloat16* __restrict__ whh_hi,
                     const __nv_bfloat16* __restrict__ whh_lo,
                     const float* __restrict__ b_ih,
                     const float* __restrict__ b_hh,
                     float* __restrict__ out32,
                     __nv_bfloat16* __restrict__ out_hi,
                     __nv_bfloat16* __restrict__ out_lo) {
    extern __shared__ __align__(16) char smem[];
    const uint32_t sb  = smem_u32(smem);
    const int tid   = threadIdx.x;
    const int wid   = tid >> 5;
    const int lane  = tid & 31;
    const int mrow0 = blockIdx.x * 64;
    const int ycol0 = blockIdx.y * 32;

    // ---- load A tiles (xhi, xlo, hhi, hlo): 64 rows x 128 bf16, pitch 272 --
    {
        const __nv_bfloat16* asrc[4] = {xhi, xlo, hhi, hlo};
        #pragma unroll
        for (int t4 = 0; t4 < 4; t4++) {
            const __nv_bfloat16* src = asrc[t4] + (size_t)mrow0 * H_;
            uint32_t dst = sb + t4 * A_TSZ;
            #pragma unroll
            for (int c = tid; c < 1024; c += 256) {     // 16B chunks
                int row = c >> 4, cw = c & 15;
                cp16(dst + row * PITCH + cw * 16, src + row * H_ + cw * 8);
            }
        }
    }
    // ---- load W tiles: 192 rows (6 groups of 32) x 128 bf16, hi then lo ----
    // gate-row g' = side*96 + gate*32 + hcol ; src row = gate*128 + ycol0 + hcol
    {
        const __nv_bfloat16* wsrc[4] = {wih_hi, whh_hi, wih_lo, whh_lo};
        #pragma unroll
        for (int part = 0; part < 2; part++) {          // 0: hi, 1: lo
            uint32_t dst = sb + SW_OFF + part * W_TSZ;
            for (int c = tid; c < 3072; c += 256) {     // 192 rows x 16 chunks
                int gp = c >> 4, cw = c & 15;
                int side = gp / 96, rem = gp % 96;
                int gate = rem >> 5, hc = rem & 31;
                const __nv_bfloat16* src = wsrc[part * 2 + side]
                    + (size_t)(gate * H_ + ycol0 + hc) * H_ + cw * 8;
                cp16(dst + gp * PITCH + cw * 16, src);
            }
        }
    }
    CP_COMMIT();
    CP_WAIT0();
    __syncthreads();

    // ---- MMA main loop -----------------------------------------------------
    const int chunk = wid >> 1;            // 0..3 gate-col chunk (48 cols)
    const int rowg  = wid & 1;             // 0..1 row group (32 rows)
    const int side  = chunk >> 1;          // 0: gi (x), 1: gh (h)
    const int mrows = rowg * 32;

    float acc[2][6][4];
    #pragma unroll
    for (int mt = 0; mt < 2; mt++)
        #pragma unroll
        for (int j = 0; j < 6; j++)
            #pragma unroll
            for (int q = 0; q < 4; q++) acc[mt][j][q] = 0.0f;

    // ldmatrix address pattern (per m-tile): row = mrows + mt*16 + (lane&15),
    // +16B for lanes 16-31 (k+8 matrices).
    const uint32_t a_lanoff = (uint32_t)(lane & 15) * PITCH
                            + ((lane >> 4) & 1) * 16;
    const uint32_t b_lanoff = (uint32_t)(chunk * 48 + (lane >> 2)) * PITCH
                            + (lane & 3) * 4;

    const int aTile[3] = {0, 0, 1};        // hi, hi, lo (offset by side*2)
    const int wBuf [3] = {0, 1, 0};        // whi, wlo, whi

    #pragma unroll
    for (int term = 0; term < 3; term++) {
        const uint32_t Abase = sb + (side * 2 + aTile[term]) * A_TSZ
                             + mrows * PITCH + a_lanoff;
        const uint32_t Bbase = sb + SW_OFF + wBuf[term] * W_TSZ + b_lanoff;
        #pragma unroll
        for (int ks = 0; ks < 8; ks++) {
            uint32_t a0[4], a1[4];
            ldmA(a0, Abase + ks * 32);
            ldmA(a1, Abase + ks * 32 + 16 * PITCH);
            #pragma unroll
            for (int j = 0; j < 6; j++) {
                uint32_t ba = Bbase + j * (8 * PITCH) + ks * 32;
                uint32_t b0 = lds32(ba);
                uint32_t b1 = lds32(ba + 16);
                hmma(acc[0][j], a0, b0, b1);
                hmma(acc[1][j], a1, b0, b1);
            }
        }
    }

    // ---- dump gates to smem (overlay W region) -----------------------------
    __syncthreads();
    #pragma unroll
    for (int mt = 0; mt < 2; mt++) {
        int row = mrows + mt * 16 + (lane >> 2);
        #pragma unroll
        for (int j = 0; j < 6; j++) {
            int col = chunk * 48 + j * 8 + 2 * (lane & 3);
            uint32_t ad = sb + SG_OFF + row * GPITCH + col * 4;
            sts2(ad,               acc[mt][j][0], acc[mt][j][1]);
            sts2(ad + 8 * GPITCH,  acc[mt][j][2], acc[mt][j][3]);
        }
    }
    __syncthreads();

    // ---- epilogue: combine gates -> h' -------------------------------------
    {
        const int hcol = tid & 31;
        const int rowb = tid >> 5;
        const int col  = ycol0 + hcol;
        const float bir = b_ih[col],       bhr = b_hh[col];
        const float biz = b_ih[128 + col], bhz = b_hh[128 + col];
        const float bin = b_ih[256 + col], bhn = b_hh[256 + col];
        #pragma unroll
        for (int rr = 0; rr < 8; rr++) {
            int row = rowb * 8 + rr;
            uint32_t base = sb + SG_OFF + row * GPITCH + hcol * 4;
            float gir = ldsf(base);
            float giz = ldsf(base + 32 * 4);
            float gin = ldsf(base + 64 * 4);
            float ghr = ldsf(base + 96 * 4);
            float ghz = ldsf(base + 128 * 4);
            float ghn = ldsf(base + 160 * 4);
            float r = sigm(gir + bir + ghr + bhr);
            float z = sigm(giz + biz + ghz + bhz);
            float n = tanh_(gin + bin + r * (ghn + bhn));
            long long idx = (long long)(mrow0 + row) * H_ + col;
            float ho = hold[idx];
            float hn = (1.0f - z) * n + z * ho;
            out32[idx] = hn;
            if (out_hi) split_store(hn, out_hi, out_lo, (int)idx);
        }
    }
}

// ---------------------------------------------------------------------------
extern "C" void kernel_launch(void* const* d_in, const int* in_sizes, int n_in,
                              void* d_out, int out_size) {
    const float* seq_out     = (const float*)d_in[0];
    const int*   target_idxs = (const int*)  d_in[1];
    const int*   nid2rows    = (const int*)  d_in[2];
    const int*   ev_nids     = (const int*)  d_in[3];
    const float* adj         = (const float*)d_in[4];
    const float* adj_bias    = (const float*)d_in[5];
    const float* w_ih        = (const float*)d_in[6];
    const float* w_hh        = (const float*)d_in[7];
    const float* b_ih        = (const float*)d_in[8];
    const float* b_hh        = (const float*)d_in[9];
    float* out = (float*)d_out;

    static bool attr_set = false;
    if (!attr_set) {
        cudaFuncSetAttribute(gru_pass_kernel,
                             cudaFuncAttributeMaxDynamicSharedMemorySize,
                             SMEM_TOT);
        attr_set = true;
    }

    prep_kernel<<<(GATES * H_ + 255) / 256, 256>>>(w_ih, w_hh);
    gather_adj_kernel<<<B_, 256>>>(seq_out, target_idxs, nid2rows, ev_nids,
                                   adj, adj_bias);

    __nv_bfloat16 *xhi_p, *xlo_p, *hhi_p, *hlo_p, *h2hi_p, *h2lo_p;
    __nv_bfloat16 *wihh_p, *wihl_p, *whhh_p, *whhl_p;
    float *h32_p, *h232_p;
    cudaGetSymbolAddress((void**)&xhi_p,  g_xhi);
    cudaGetSymbolAddress((void**)&xlo_p,  g_xlo);
    cudaGetSymbolAddress((void**)&hhi_p,  g_hhi);
    cudaGetSymbolAddress((void**)&hlo_p,  g_hlo);
    cudaGetSymbolAddress((void**)&h2hi_p, g_h2hi);
    cudaGetSymbolAddress((void**)&h2lo_p, g_h2lo);
    cudaGetSymbolAddress((void**)&h32_p,  g_h32);
    cudaGetSymbolAddress((void**)&h232_p, g_h232);
    cudaGetSymbolAddress((void**)&wihh_p, g_wih_hi);
    cudaGetSymbolAddress((void**)&wihl_p, g_wih_lo);
    cudaGetSymbolAddress((void**)&whhh_p, g_whh_hi);
    cudaGetSymbolAddress((void**)&whhl_p, g_whh_lo);

    dim3 grid(MTOT / 64, 4);
    // pass 1: x = a, h = ev  -> h1 (fp32 + bf16 splits into fresh buffers)
    gru_pass_kernel<<<grid, 256, SMEM_TOT>>>(
        xhi_p, xlo_p, hhi_p, hlo_p, h32_p,
        wihh_p, wihl_p, whhh_p, whhl_p, b_ih, b_hh,
        h232_p, h2hi_p, h2lo_p);
    // pass 2: x = h = h1 -> d_out
    gru_pass_kernel<<<grid, 256, SMEM_TOT>>>(
        h2hi_p, h2lo_p, h2hi_p, h2lo_p, h232_p,
        wihh_p, wihl_p, whhh_p, whhl_p, b_ih, b_hh,
        out, nullptr, nullptr);
}